// round 8
// baseline (speedup 1.0000x reference)
#include <cuda_runtime.h>
#include <cstdint>
#include <math.h>

// IMLE sampler: out[s,b,n] = 1 iff (logits[b,n] + Gumbel(noise[s,b,n])) is in
// the row's top-k.  S=16, B=128, N=16384, k=32.
//
// v8 = v7 + real MLP:
//   - launch_bounds(256,5): 51 regs/thread
//   - explicit 4-wide load batching into register arrays (8 LDG.128 in
//     flight per thread) with outer loop kept rolled
//   - prep split: row_sum (reduction) + thresh (fully parallel)
// main: per-row CTA: barrier-free stream (1 cmp/elem) -> smem candidates ->
//       fast keys -> O(c^2) kth -> exact double-log band recompute ->
//       exact rank, lowest-index tie-break (matches jax.lax.top_k).

#define NCOLS    16384
#define NV4      (NCOLS/4)
#define LOG2N    14
#define THREADS  256
#define ITERS    (NV4/THREADS)   // 16
#define BATCH    4
#define MAXLROWS 256
#define CAP      1024
#define SURV     512
#define TARGETC  128.0f
#define DELTA    0.05f

__device__ float g_U[(size_t)MAXLROWS * NCOLS];
__device__ float g_C2[MAXLROWS];

__device__ __forceinline__ unsigned f2k(float f) {
    unsigned b = __float_as_uint(f);
    return b ^ ((unsigned)((int)b >> 31) | 0x80000000u);
}
__device__ __forceinline__ float k2f(unsigned k) {
    unsigned b = (k & 0x80000000u) ? (k ^ 0x80000000u) : ~k;
    return __uint_as_float(b);
}
// float32 log chain, correctly rounded via double (immune to fast-math):
// t1=log(u); t3=log(-t1); p = logit - t3   (matches reference op-by-op)
__device__ __forceinline__ float exact_perturb(float u, float lg) {
    float t1 = (float)log((double)u);
    float t3 = (float)log((double)(-t1));
    return lg + (-t3);
}

// ---------------------------------------------------------------------------
__global__ __launch_bounds__(1024)
void row_sum(const float* __restrict__ logits)
{
    __shared__ float red[32];
    const int row = blockIdx.x, tid = threadIdx.x;
    const int lane = tid & 31, warp = tid >> 5;
    const float4* L4 = reinterpret_cast<const float4*>(logits + (size_t)row * NCOLS);

    float s = 0.f;
    #pragma unroll
    for (int c = 0; c < NV4 / 1024; ++c) {
        float4 l = __ldg(&L4[tid + c * 1024]);
        s += __expf(l.x) + __expf(l.y) + __expf(l.z) + __expf(l.w);
    }
    #pragma unroll
    for (int off = 16; off; off >>= 1) s += __shfl_xor_sync(~0u, s, off);
    if (lane == 0) red[warp] = s;
    __syncthreads();
    if (warp == 0) {
        float t = red[lane];
        #pragma unroll
        for (int off = 16; off; off >>= 1) t += __shfl_xor_sync(~0u, t, off);
        if (lane == 0) g_C2[row] = TARGETC / t;
    }
}

// ---------------------------------------------------------------------------
__global__ __launch_bounds__(256)
void thresh_kernel(const float* __restrict__ logits, int total4)
{
    int i = blockIdx.x * 256 + threadIdx.x;          // float4 index
    if (i >= total4) return;
    int row = (4 * i) >> LOG2N;
    const float MC = -g_C2[row] * 1.4426950408889634f * 1.01f;
    float4 l = __ldg(&reinterpret_cast<const float4*>(logits)[i]);
    float4 U;
    U.x = exp2f(MC * __expf(l.x) - 1e-6f);
    U.y = exp2f(MC * __expf(l.y) - 1e-6f);
    U.z = exp2f(MC * __expf(l.z) - 1e-6f);
    U.w = exp2f(MC * __expf(l.w) - 1e-6f);
    if (!(U.x == U.x)) U.x = 0.f;   // NaN -> always candidate
    if (!(U.y == U.y)) U.y = 0.f;
    if (!(U.z == U.z)) U.z = 0.f;
    if (!(U.w == U.w)) U.w = 0.f;
    reinterpret_cast<float4*>(g_U)[i] = U;
}

// ---------------------------------------------------------------------------
__device__ __forceinline__ void cand4(float4 u, float4 U, int v,
                                      int* s_cnt, unsigned* s_cu, int* s_ci)
{
    bool b0 = u.x >= U.x, b1 = u.y >= U.y, b2 = u.z >= U.z, b3 = u.w >= U.w;
    if (b0 | b1 | b2 | b3) {                       // rare (~2.8% of float4s)
        if (b0) { int p = atomicAdd(s_cnt, 1); if (p < CAP) { s_cu[p] = __float_as_uint(u.x); s_ci[p] = 4*v+0; } }
        if (b1) { int p = atomicAdd(s_cnt, 1); if (p < CAP) { s_cu[p] = __float_as_uint(u.y); s_ci[p] = 4*v+1; } }
        if (b2) { int p = atomicAdd(s_cnt, 1); if (p < CAP) { s_cu[p] = __float_as_uint(u.z); s_ci[p] = 4*v+2; } }
        if (b3) { int p = atomicAdd(s_cnt, 1); if (p < CAP) { s_cu[p] = __float_as_uint(u.w); s_ci[p] = 4*v+3; } }
    }
}

__global__ __launch_bounds__(THREADS, 5)
void main_kernel(const float* __restrict__ noise,
                 const float* __restrict__ logits,
                 const int* __restrict__ kptr,
                 float* __restrict__ out, int Brows)
{
    __shared__ unsigned s_cu[CAP];      // candidate u bits
    __shared__ int      s_ci[CAP];      // candidate index in row
    __shared__ unsigned s_key[CAP];     // fast perturbed-logit keys
    __shared__ float    e_val[SURV];
    __shared__ int      e_idx[SURV];
    __shared__ int      s_cnt, s_scnt, s_tot;
    __shared__ unsigned s_kth;

    const int row = blockIdx.x, tid = threadIdx.x;
    const int lane = tid & 31, warp = tid >> 5;
    const int lrow = row % Brows;
    const size_t rowoff = (size_t)row * NCOLS;
    const size_t logoff = (size_t)lrow * NCOLS;

    if (tid == 0) { s_cnt = 0; s_scnt = 0; s_kth = 0xFFFFFFFFu; }
    __syncthreads();

    int kk = kptr ? __ldg(kptr) : 32;
    if (kk < 1) kk = 1;
    if (kk > NCOLS) kk = NCOLS;

    // ---- Phase A: barrier-free stream; 8 LDG.128 front-batched ----
    {
        const float4* n4 = reinterpret_cast<const float4*>(noise + rowoff);
        const float4* t4 = reinterpret_cast<const float4*>(g_U + (size_t)lrow * NCOLS);
        float4*       o4 = reinterpret_cast<float4*>(out + rowoff);
        const float4 z4 = make_float4(0.f, 0.f, 0.f, 0.f);
        #pragma unroll 1
        for (int c = 0; c < ITERS; c += BATCH) {
            float4 u[BATCH], U[BATCH];
            #pragma unroll
            for (int b = 0; b < BATCH; ++b) {
                int v = tid + (c + b) * THREADS;
                u[b] = __ldcs(&n4[v]);
                U[b] = __ldg(&t4[v]);
            }
            #pragma unroll
            for (int b = 0; b < BATCH; ++b)
                __stcs(&o4[tid + (c + b) * THREADS], z4);
            #pragma unroll
            for (int b = 0; b < BATCH; ++b)
                cand4(u[b], U[b], tid + (c + b) * THREADS, &s_cnt, s_cu, s_ci);
        }
    }
    __syncthreads();
    int cnt = s_cnt;

    // ---- Fallback: widening rescan (unreachable on sane data) ----
    if (cnt < kk || cnt > CAP) {
        const float INV_LN2 = 1.4426950408889634f;
        float C2 = g_C2[lrow];
        float s = 1.0f, sHi = -1.0f;
        int chosen = 0;
        for (int it = 0; it < 64 && !chosen; ++it) {
            int c = 0;
            for (int v = tid; v < NCOLS; v += THREADS) {
                float t = __log2f(noise[rowoff + v]);
                float g = -C2 * __expf(logits[logoff + v]) * INV_LN2 * s - 1e-6f;
                c += (!(g == g) || t >= g) ? 1 : 0;
            }
            #pragma unroll
            for (int off = 16; off; off >>= 1) c += __shfl_xor_sync(~0u, c, off);
            if (lane == 0) s_key[warp] = (unsigned)c;   // scratch
            __syncthreads();
            if (tid == 0) {
                int tot = 0;
                for (int wg = 0; wg < THREADS / 32; ++wg) tot += (int)s_key[wg];
                s_tot = tot;
            }
            __syncthreads();
            int tot = s_tot;
            if (tot >= kk && (sHi < 0.f || s < sHi)) sHi = s;
            if (tot >= kk && tot <= CAP) chosen = 1;
            else if (tot < kk) s *= 4.0f;
            else s *= 0.70710678f;
            __syncthreads();
        }
        if (!chosen) s = (sHi > 0.f) ? sHi : 1e30f;
        if (tid == 0) s_cnt = 0;
        __syncthreads();
        for (int v = tid; v < NCOLS; v += THREADS) {
            float uu = noise[rowoff + v];
            float t  = __log2f(uu);
            float g  = -C2 * __expf(logits[logoff + v]) * INV_LN2 * s - 1e-6f;
            if (!(g == g) || t >= g) {
                int p = atomicAdd(&s_cnt, 1);
                if (p < CAP) { s_cu[p] = __float_as_uint(uu); s_ci[p] = v; }
            }
        }
        __syncthreads();
        cnt = s_cnt;
        if (cnt > CAP) cnt = CAP;
        if (cnt == 0) return;
    }
    if (cnt > CAP) cnt = CAP;
    if (kk > cnt) kk = cnt;

    // ---- Phase B: fast keys (monotone uint; NaN -> max) ----
    for (int i = tid; i < cnt; i += THREADS) {
        float u  = __uint_as_float(s_cu[i]);
        float lg = __ldg(&logits[logoff + s_ci[i]]);
        float p  = lg - __logf(-__logf(u));
        s_key[i] = (p == p) ? f2k(p) : 0xFFFFFFFFu;
    }
    __syncthreads();

    // ---- Phase C: O(c^2) rank count; kth fast key via atomicMin ----
    for (int i = tid; i < cnt; i += THREADS) {
        unsigned ki = s_key[i];
        int r = 0;
        for (int j = 0; j < cnt; ++j) r += (s_key[j] > ki);
        if (r < kk) atomicMin(&s_kth, ki);
    }
    __syncthreads();

    unsigned kth = s_kth;
    float kf = k2f(kth);
    unsigned cut = (kf == kf && kf < 1e30f && kf > -1e30f)
                   ? f2k(kf - DELTA) : kth;

    // ---- Phase D: band survivors -> exact recompute ----
    for (int i = tid; i < cnt; i += THREADS) {
        if (s_key[i] >= cut) {
            int p = atomicAdd(&s_scnt, 1);
            if (p < SURV) {
                float u  = __uint_as_float(s_cu[i]);
                float lg = __ldg(&logits[logoff + s_ci[i]]);
                e_val[p] = exact_perturb(u, lg);
                e_idx[p] = s_ci[i];
            }
        }
    }
    __syncthreads();
    int sc = s_scnt;
    if (sc > SURV) sc = SURV;

    // ---- Phase E: exact O(sc^2) rank, lowest-index tie-break ----
    for (int i = tid; i < sc; i += THREADS) {
        float pi = e_val[i];
        int   ii = e_idx[i];
        int r = 0;
        for (int j = 0; j < sc; ++j) {
            float pj = e_val[j];
            r += (pj > pi) || (pj == pi && e_idx[j] < ii);
        }
        if (r < kk) out[rowoff + ii] = 1.0f;
    }
}

// ---------------------------------------------------------------------------
extern "C" void kernel_launch(void* const* d_in, const int* in_sizes, int n_in,
                              void* d_out, int out_size) {
    int iK = -1, iU = -1, iL = -1;
    for (int i = 0; i < n_in; ++i)
        if (in_sizes[i] == 1) iK = i;
    long best = -1;
    for (int i = 0; i < n_in; ++i) {
        if (i == iK) continue;
        if ((long)in_sizes[i] > best) { best = in_sizes[i]; iU = i; }
    }
    for (int i = 0; i < n_in; ++i)
        if (i != iK && i != iU) { iL = i; break; }

    const float* logits = (const float*)d_in[iL];
    const float* noise  = (const float*)d_in[iU];
    const int*   kptr   = (iK >= 0) ? (const int*)d_in[iK] : nullptr;
    float* out = (float*)d_out;

    int rows  = in_sizes[iU] / NCOLS;   // S*B = 2048
    int Brows = in_sizes[iL] / NCOLS;   // B   = 128
    if (Brows > MAXLROWS) Brows = MAXLROWS;
    int nlog4 = (Brows * NCOLS) / 4;

    row_sum<<<Brows, 1024>>>(logits);
    thresh_kernel<<<(nlog4 + 255) / 256, 256>>>(logits, nlog4);
    main_kernel<<<rows, THREADS>>>(noise, logits, kptr, out, Brows);
}

// round 9
// speedup vs baseline: 1.0623x; 1.0623x over previous
#include <cuda_runtime.h>
#include <cstdint>
#include <math.h>

// IMLE sampler: out[s,b,n] = 1 iff (logits[b,n] + Gumbel(noise[s,b,n])) is in
// the row's top-k.  S=16, B=128, N=16384, k=32.
//
// v9 = v7 stream + smaller tail + thinner threshold stream:
//   - TARGETC 64 (candidates ~64/row): tail phases 2-3x cheaper
//   - bf16 u-space thresholds (truncated-down = conservative): half the
//     threshold traffic (LDG.64), exact level-set of true perturbed logit
//   - prep: 512-CTA partial row sums (deterministic) + parallel thresh
// main: per-row CTA: barrier-free stream (cmp vs bf16 threshold) -> smem
//       candidates -> fast keys -> O(c^2) kth -> exact double-log band
//       recompute -> exact rank, lowest-index tie-break (jax.lax.top_k).

#define NCOLS    16384
#define NV4      (NCOLS/4)
#define THREADS  256
#define ITERS    (NV4/THREADS)   // 16
#define MAXLROWS 256
#define CAP      1024
#define SURV     512
#define TARGETC  64.0f
#define DELTA    0.05f

__device__ unsigned short g_Ub[(size_t)MAXLROWS * NCOLS];  // bf16 thresholds
__device__ float g_part[MAXLROWS * 4];                     // quarter-row sums

__device__ __forceinline__ unsigned f2k(float f) {
    unsigned b = __float_as_uint(f);
    return b ^ ((unsigned)((int)b >> 31) | 0x80000000u);
}
__device__ __forceinline__ float k2f(unsigned k) {
    unsigned b = (k & 0x80000000u) ? (k ^ 0x80000000u) : ~k;
    return __uint_as_float(b);
}
// float32 log chain, correctly rounded via double (immune to fast-math):
// t1=log(u); t3=log(-t1); p = logit - t3   (matches reference op-by-op)
__device__ __forceinline__ float exact_perturb(float u, float lg) {
    float t1 = (float)log((double)u);
    float t3 = (float)log((double)(-t1));
    return lg + (-t3);
}

// ---------------------------------------------------------------------------
// 4 CTAs per logits row; each sums a quarter row (no atomics -> deterministic)
__global__ __launch_bounds__(256)
void row_sum_part(const float* __restrict__ logits)
{
    __shared__ float red[8];
    const int part = blockIdx.x;            // row*4 + q
    const int tid = threadIdx.x, lane = tid & 31, warp = tid >> 5;
    const float4* L4 = reinterpret_cast<const float4*>(logits) + part * (NV4 / 4);

    float s = 0.f;
    #pragma unroll
    for (int c = 0; c < NV4 / 4 / 256; ++c) {      // 4 float4 per thread
        float4 l = __ldg(&L4[tid + c * 256]);
        s += __expf(l.x) + __expf(l.y) + __expf(l.z) + __expf(l.w);
    }
    #pragma unroll
    for (int off = 16; off; off >>= 1) s += __shfl_xor_sync(~0u, s, off);
    if (lane == 0) red[warp] = s;
    __syncthreads();
    if (tid == 0) {
        float t = 0.f;
        #pragma unroll
        for (int w = 0; w < 8; ++w) t += red[w];
        g_part[part] = t;
    }
}

// ---------------------------------------------------------------------------
__global__ __launch_bounds__(256)
void thresh_kernel(const float* __restrict__ logits, int total4)
{
    int i = blockIdx.x * 256 + threadIdx.x;          // float4 index
    if (i >= total4) return;
    int row = i >> 12;                               // (4i)/16384
    float S = g_part[4*row] + g_part[4*row+1] + g_part[4*row+2] + g_part[4*row+3];
    const float MC = -(TARGETC / S) * 1.4426950408889634f * 1.01f;
    float4 l = __ldg(&reinterpret_cast<const float4*>(logits)[i]);
    float U0 = exp2f(MC * __expf(l.x) - 1e-6f);
    float U1 = exp2f(MC * __expf(l.y) - 1e-6f);
    float U2 = exp2f(MC * __expf(l.z) - 1e-6f);
    float U3 = exp2f(MC * __expf(l.w) - 1e-6f);
    if (!(U0 == U0)) U0 = 0.f;   // NaN -> always candidate
    if (!(U1 == U1)) U1 = 0.f;
    if (!(U2 == U2)) U2 = 0.f;
    if (!(U3 == U3)) U3 = 0.f;
    // truncate toward zero: bf16 <= fp32 value -> conservative widening
    unsigned b0 = __float_as_uint(U0) >> 16;
    unsigned b1 = __float_as_uint(U1) >> 16;
    unsigned b2 = __float_as_uint(U2) >> 16;
    unsigned b3 = __float_as_uint(U3) >> 16;
    uint2 packed = make_uint2(b0 | (b1 << 16), b2 | (b3 << 16));
    reinterpret_cast<uint2*>(g_Ub)[i] = packed;
}

// ---------------------------------------------------------------------------
__device__ __forceinline__ void cand4(float4 u, uint2 Uw, int v,
                                      int* s_cnt, unsigned* s_cu, int* s_ci)
{
    float U0 = __uint_as_float(Uw.x << 16);
    float U1 = __uint_as_float(Uw.x & 0xFFFF0000u);
    float U2 = __uint_as_float(Uw.y << 16);
    float U3 = __uint_as_float(Uw.y & 0xFFFF0000u);
    bool b0 = u.x >= U0, b1 = u.y >= U1, b2 = u.z >= U2, b3 = u.w >= U3;
    if (b0 | b1 | b2 | b3) {                       // rare (~1.5% of float4s)
        if (b0) { int p = atomicAdd(s_cnt, 1); if (p < CAP) { s_cu[p] = __float_as_uint(u.x); s_ci[p] = 4*v+0; } }
        if (b1) { int p = atomicAdd(s_cnt, 1); if (p < CAP) { s_cu[p] = __float_as_uint(u.y); s_ci[p] = 4*v+1; } }
        if (b2) { int p = atomicAdd(s_cnt, 1); if (p < CAP) { s_cu[p] = __float_as_uint(u.z); s_ci[p] = 4*v+2; } }
        if (b3) { int p = atomicAdd(s_cnt, 1); if (p < CAP) { s_cu[p] = __float_as_uint(u.w); s_ci[p] = 4*v+3; } }
    }
}

__global__ __launch_bounds__(THREADS, 6)
void main_kernel(const float* __restrict__ noise,
                 const float* __restrict__ logits,
                 const int* __restrict__ kptr,
                 float* __restrict__ out, int Brows)
{
    __shared__ unsigned s_cu[CAP];      // candidate u bits
    __shared__ int      s_ci[CAP];      // candidate index in row
    __shared__ unsigned s_key[CAP];     // fast perturbed-logit keys
    __shared__ float    e_val[SURV];
    __shared__ int      e_idx[SURV];
    __shared__ int      s_cnt, s_scnt, s_tot;
    __shared__ unsigned s_kth;

    const int row = blockIdx.x, tid = threadIdx.x;
    const int lane = tid & 31, warp = tid >> 5;
    const int lrow = row % Brows;
    const size_t rowoff = (size_t)row * NCOLS;
    const size_t logoff = (size_t)lrow * NCOLS;

    if (tid == 0) { s_cnt = 0; s_scnt = 0; s_kth = 0xFFFFFFFFu; }
    __syncthreads();

    int kk = kptr ? __ldg(kptr) : 32;
    if (kk < 1) kk = 1;
    if (kk > NCOLS) kk = NCOLS;

    // ---- Phase A: barrier-free stream (v7 shape + bf16 thresholds) ----
    {
        const float4* n4 = reinterpret_cast<const float4*>(noise + rowoff);
        const uint2*  t2 = reinterpret_cast<const uint2*>(g_Ub + (size_t)lrow * NCOLS);
        float4*       o4 = reinterpret_cast<float4*>(out + rowoff);
        const float4 z4 = make_float4(0.f, 0.f, 0.f, 0.f);
        #pragma unroll
        for (int c = 0; c < ITERS / 2; ++c) {
            int v0 = tid + (2*c) * THREADS;
            int v1 = v0 + THREADS;
            float4 u0 = __ldcs(&n4[v0]);
            uint2  U0 = __ldg(&t2[v0]);
            float4 u1 = __ldcs(&n4[v1]);
            uint2  U1 = __ldg(&t2[v1]);
            __stcs(&o4[v0], z4);
            __stcs(&o4[v1], z4);
            cand4(u0, U0, v0, &s_cnt, s_cu, s_ci);
            cand4(u1, U1, v1, &s_cnt, s_cu, s_ci);
        }
    }
    __syncthreads();
    int cnt = s_cnt;

    // ---- Fallback: widening rescan (fires ~0.003% of rows) ----
    if (cnt < kk || cnt > CAP) {
        const float INV_LN2 = 1.4426950408889634f;
        float S = g_part[4*lrow] + g_part[4*lrow+1] + g_part[4*lrow+2] + g_part[4*lrow+3];
        float C2 = TARGETC / S;
        float s = 1.0f, sHi = -1.0f;
        int chosen = 0;
        for (int it = 0; it < 64 && !chosen; ++it) {
            int c = 0;
            for (int v = tid; v < NCOLS; v += THREADS) {
                float t = __log2f(noise[rowoff + v]);
                float g = -C2 * __expf(logits[logoff + v]) * INV_LN2 * s - 1e-6f;
                c += (!(g == g) || t >= g) ? 1 : 0;
            }
            #pragma unroll
            for (int off = 16; off; off >>= 1) c += __shfl_xor_sync(~0u, c, off);
            if (lane == 0) s_key[warp] = (unsigned)c;   // scratch
            __syncthreads();
            if (tid == 0) {
                int tot = 0;
                for (int wg = 0; wg < THREADS / 32; ++wg) tot += (int)s_key[wg];
                s_tot = tot;
            }
            __syncthreads();
            int tot = s_tot;
            if (tot >= kk && (sHi < 0.f || s < sHi)) sHi = s;
            if (tot >= kk && tot <= CAP) chosen = 1;
            else if (tot < kk) s *= 4.0f;
            else s *= 0.70710678f;
            __syncthreads();
        }
        if (!chosen) s = (sHi > 0.f) ? sHi : 1e30f;
        if (tid == 0) s_cnt = 0;
        __syncthreads();
        for (int v = tid; v < NCOLS; v += THREADS) {
            float uu = noise[rowoff + v];
            float t  = __log2f(uu);
            float g  = -C2 * __expf(logits[logoff + v]) * INV_LN2 * s - 1e-6f;
            if (!(g == g) || t >= g) {
                int p = atomicAdd(&s_cnt, 1);
                if (p < CAP) { s_cu[p] = __float_as_uint(uu); s_ci[p] = v; }
            }
        }
        __syncthreads();
        cnt = s_cnt;
        if (cnt > CAP) cnt = CAP;
        if (cnt == 0) return;
    }
    if (cnt > CAP) cnt = CAP;
    if (kk > cnt) kk = cnt;

    // ---- Phase B: fast keys (monotone uint; NaN -> max) ----
    for (int i = tid; i < cnt; i += THREADS) {
        float u  = __uint_as_float(s_cu[i]);
        float lg = __ldg(&logits[logoff + s_ci[i]]);
        float p  = lg - __logf(-__logf(u));
        s_key[i] = (p == p) ? f2k(p) : 0xFFFFFFFFu;
    }
    __syncthreads();

    // ---- Phase C: O(c^2) rank count; kth fast key via atomicMin ----
    for (int i = tid; i < cnt; i += THREADS) {
        unsigned ki = s_key[i];
        int r = 0;
        for (int j = 0; j < cnt; ++j) r += (s_key[j] > ki);
        if (r < kk) atomicMin(&s_kth, ki);
    }
    __syncthreads();

    unsigned kth = s_kth;
    float kf = k2f(kth);
    unsigned cut = (kf == kf && kf < 1e30f && kf > -1e30f)
                   ? f2k(kf - DELTA) : kth;

    // ---- Phase D: band survivors -> exact recompute ----
    for (int i = tid; i < cnt; i += THREADS) {
        if (s_key[i] >= cut) {
            int p = atomicAdd(&s_scnt, 1);
            if (p < SURV) {
                float u  = __uint_as_float(s_cu[i]);
                float lg = __ldg(&logits[logoff + s_ci[i]]);
                e_val[p] = exact_perturb(u, lg);
                e_idx[p] = s_ci[i];
            }
        }
    }
    __syncthreads();
    int sc = s_scnt;
    if (sc > SURV) sc = SURV;

    // ---- Phase E: exact O(sc^2) rank, lowest-index tie-break ----
    for (int i = tid; i < sc; i += THREADS) {
        float pi = e_val[i];
        int   ii = e_idx[i];
        int r = 0;
        for (int j = 0; j < sc; ++j) {
            float pj = e_val[j];
            r += (pj > pi) || (pj == pi && e_idx[j] < ii);
        }
        if (r < kk) out[rowoff + ii] = 1.0f;
    }
}

// ---------------------------------------------------------------------------
extern "C" void kernel_launch(void* const* d_in, const int* in_sizes, int n_in,
                              void* d_out, int out_size) {
    int iK = -1, iU = -1, iL = -1;
    for (int i = 0; i < n_in; ++i)
        if (in_sizes[i] == 1) iK = i;
    long best = -1;
    for (int i = 0; i < n_in; ++i) {
        if (i == iK) continue;
        if ((long)in_sizes[i] > best) { best = in_sizes[i]; iU = i; }
    }
    for (int i = 0; i < n_in; ++i)
        if (i != iK && i != iU) { iL = i; break; }

    const float* logits = (const float*)d_in[iL];
    const float* noise  = (const float*)d_in[iU];
    const int*   kptr   = (iK >= 0) ? (const int*)d_in[iK] : nullptr;
    float* out = (float*)d_out;

    int rows  = in_sizes[iU] / NCOLS;   // S*B = 2048
    int Brows = in_sizes[iL] / NCOLS;   // B   = 128
    if (Brows > MAXLROWS) Brows = MAXLROWS;
    int nlog4 = (Brows * NCOLS) / 4;

    row_sum_part<<<Brows * 4, 256>>>(logits);
    thresh_kernel<<<(nlog4 + 255) / 256, 256>>>(logits, nlog4);
    main_kernel<<<rows, THREADS>>>(noise, logits, kptr, out, Brows);
}